// round 3
// baseline (speedup 1.0000x reference)
#include <cuda_runtime.h>
#include <cstdint>

#define NUM_B 16
#define SEQ_N 1025
#define NHEAD 12
#define HDIM  64
#define DMODEL 768
#define M_ROWS (NUM_B * SEQ_N)   // 16400

// ---------------- scratch ----------------
__device__ float g_Q[NUM_B * NHEAD * SEQ_N * HDIM];
__device__ float g_K[NUM_B * NHEAD * SEQ_N * HDIM];
__device__ float g_V[NUM_B * NHEAD * SEQ_N * HDIM];
__device__ float g_ctx[NUM_B * SEQ_N * DMODEL];

__device__ __forceinline__ uint32_t f2tf(float f) {
    uint32_t r;
    asm("cvt.rna.tf32.f32 %0, %1;" : "=r"(r) : "f"(f));
    return r;
}
__device__ __forceinline__ void mma8(float* c, const uint32_t* a, const uint32_t* b) {
    asm volatile(
        "mma.sync.aligned.m16n8k8.row.col.f32.tf32.tf32.f32 "
        "{%0,%1,%2,%3}, {%4,%5,%6,%7}, {%8,%9}, {%0,%1,%2,%3};\n"
        : "+f"(c[0]), "+f"(c[1]), "+f"(c[2]), "+f"(c[3])
        : "r"(a[0]), "r"(a[1]), "r"(a[2]), "r"(a[3]), "r"(b[0]), "r"(b[1]));
}

// =================================================================
// TN GEMM, tf32 TC. Block 128x128, 4 warps (64x64 warp tile), k-step 16.
// Fragment-packed smem: A frag = 1 LDS.128, B frag = 1 LDS.64.
// MODE 0: RoPE epilogue -> g_Q/g_K/g_V. MODE 1: +bias -> out.
// =================================================================
template<int MODE>
__global__ __launch_bounds__(128) void gemm_tc(
    const float* __restrict__ A, const float* __restrict__ Bw,
    float* __restrict__ out, const float* __restrict__ bias,
    const float* __restrict__ freqs)
{
    // Apk: mb(8) x kb(2) x lane(32) x reg(4)  = 2048 u32
    // Bpk: nb(16) x kb(2) x lane(32) x reg(2) = 2048 u32
    __shared__ uint32_t Apk[2048];
    __shared__ uint32_t Bpk[2048];

    const int tid = threadIdx.x;
    const int lane = tid & 31;
    const int wid = tid >> 5;
    const int wm = wid & 1;
    const int wn = wid >> 1;
    const int m0 = blockIdx.x * 128;
    const int n0 = blockIdx.y * 128;

    const float* Ap = (MODE == 1) ? g_ctx : A;

    float c[4][8][4];
#pragma unroll
    for (int i = 0; i < 4; i++)
#pragma unroll
        for (int j = 0; j < 8; j++)
#pragma unroll
            for (int r = 0; r < 4; r++) c[i][j][r] = 0.f;

    const int lr = tid >> 2;            // 0..31
    const int c4 = (tid & 3) * 4;       // 0,4,8,12
    const int kb_st = c4 >> 3;          // 0/1
    const int regA = ((c4 >> 2) & 1) << 1;   // 0 or 2
    const int regB = (c4 >> 2) & 1;          // 0 or 1

    for (int k0 = 0; k0 < DMODEL; k0 += 16) {
        // ---- stage A (128x16) ----
#pragma unroll
        for (int p = 0; p < 4; p++) {
            int m = lr + p * 32;
            int gm = m0 + m;
            float4 v = make_float4(0.f, 0.f, 0.f, 0.f);
            if (gm < M_ROWS) v = *(const float4*)&Ap[(size_t)gm * DMODEL + k0 + c4];
            uint32_t* pp = &Apk[(((m >> 4) * 2 + kb_st) << 7) + ((m & 7) << 4)
                                + regA + ((m >> 3) & 1)];
            pp[0]  = f2tf(v.x);
            pp[4]  = f2tf(v.y);
            pp[8]  = f2tf(v.z);
            pp[12] = f2tf(v.w);
        }
        // ---- stage B (128x16) ----
#pragma unroll
        for (int p = 0; p < 4; p++) {
            int n = lr + p * 32;
            float4 v = *(const float4*)&Bw[(size_t)(n0 + n) * DMODEL + k0 + c4];
            uint32_t* pp = &Bpk[(((n >> 3) * 2 + kb_st) << 6) + ((n & 7) << 3) + regB];
            pp[0] = f2tf(v.x);
            pp[2] = f2tf(v.y);
            pp[4] = f2tf(v.z);
            pp[6] = f2tf(v.w);
        }
        __syncthreads();

#pragma unroll
        for (int kb = 0; kb < 2; kb++) {
            uint32_t a[4][4];
            uint32_t b[8][2];
#pragma unroll
            for (int mt = 0; mt < 4; mt++) {
                uint4 av = *(const uint4*)&Apk[(((wm * 4 + mt) * 2 + kb) << 7) + lane * 4];
                a[mt][0] = av.x; a[mt][1] = av.y; a[mt][2] = av.z; a[mt][3] = av.w;
            }
#pragma unroll
            for (int nt = 0; nt < 8; nt++) {
                uint2 bv = *(const uint2*)&Bpk[(((wn * 8 + nt) * 2 + kb) << 6) + lane * 2];
                b[nt][0] = bv.x; b[nt][1] = bv.y;
            }
#pragma unroll
            for (int mt = 0; mt < 4; mt++)
#pragma unroll
                for (int nt = 0; nt < 8; nt++)
                    mma8(c[mt][nt], a[mt], b[nt]);
        }
        __syncthreads();
    }

    // -------- epilogue --------
    if (MODE == 0) {
        const int sidx = n0 / DMODEL;                 // uniform per block
        const int hh = ((n0 % DMODEL) >> 6) + wn;     // uniform per warp
        float* dst = (sidx == 0) ? g_Q : (sidx == 1) ? g_K : g_V;
#pragma unroll
        for (int nt = 0; nt < 8; nt++) {
            int e0 = nt * 8 + 2 * (lane & 3);
            float f0 = 0.f, f1 = 0.f;
            if (sidx < 2) {
                int fi = hh * 32 + (e0 >> 1);
                f0 = freqs[fi];
                f1 = freqs[384 + fi];
            }
#pragma unroll
            for (int mt = 0; mt < 4; mt++)
#pragma unroll
                for (int hr = 0; hr < 2; hr++) {
                    int row = m0 + wm * 64 + mt * 16 + (lane >> 2) + hr * 8;
                    if (row >= M_ROWS) continue;
                    int bb = row / SEQ_N;
                    int n = row - bb * SEQ_N;
                    float v0 = c[mt][nt][hr * 2 + 0];
                    float v1 = c[mt][nt][hr * 2 + 1];
                    if (sidx < 2 && n >= 1) {
                        int t = n - 1;
                        float ang = (float)(t & 31) * f0 + (float)(t >> 5) * f1;
                        float sn, cs;
                        sincosf(ang, &sn, &cs);
                        float a0 = v0, b0 = v1;
                        v0 = a0 * cs - b0 * sn;
                        v1 = a0 * sn + b0 * cs;
                    }
                    size_t off = ((size_t)((bb * NHEAD + hh) * SEQ_N + n)) * HDIM + e0;
                    *(float2*)&dst[off] = make_float2(v0, v1);
                }
        }
    } else {
#pragma unroll
        for (int nt = 0; nt < 8; nt++) {
            int col = n0 + wn * 64 + nt * 8 + 2 * (lane & 3);
            float b0v = bias[col], b1v = bias[col + 1];
#pragma unroll
            for (int mt = 0; mt < 4; mt++)
#pragma unroll
                for (int hr = 0; hr < 2; hr++) {
                    int row = m0 + wm * 64 + mt * 16 + (lane >> 2) + hr * 8;
                    if (row >= M_ROWS) continue;
                    *(float2*)&out[(size_t)row * DMODEL + col] =
                        make_float2(c[mt][nt][hr * 2 + 0] + b0v,
                                    c[mt][nt][hr * 2 + 1] + b1v);
                }
        }
    }
}

// =================================================================
// Flash attention, tf32 TC. 256 threads (8 warps), 128 queries/block,
// 16 q/warp, kv tiles of 64. Fragment-packed K/V (shared) and
// Q/P (warp-private strips).
// smem u32: Kpk 4096 | Vpk 4096 | Qpk 8192 | Ppk 8192 = 96 KB
// =================================================================
#define ATTN_SMEM_BYTES (24576 * 4)

__global__ __launch_bounds__(256) void attn_tc()
{
    extern __shared__ uint32_t dsm[];
    uint32_t* Kpk = dsm;           // nb(8) x kb(8) x lane(32) x reg(2)
    uint32_t* Vpk = dsm + 4096;    // nb(8) x kb(8) x lane(32) x reg(2)
    uint32_t* Qpk = dsm + 8192;    // w(8) x kb(8) x lane(32) x reg(4)
    uint32_t* Ppk = dsm + 16384;   // w(8) x kb(8) x lane(32) x reg(4)

    const int tid = threadIdx.x;
    const int lane = tid & 31;
    const int w = tid >> 5;
    const int q0 = blockIdx.x * 128;
    const int bh = blockIdx.y;
    const size_t base = (size_t)bh * SEQ_N * HDIM;
    uint32_t* Qw = Qpk + w * 1024;
    uint32_t* Pw = Ppk + w * 1024;

    // ---- stage Q (scaled, packed A-frag layout), warp-private ----
#pragma unroll
    for (int it = 0; it < 8; it++) {
        int slot = lane + it * 32;          // 256 slots = 16 rows x 16 float4
        int r = slot >> 4;
        int cg = (slot & 15) * 4;
        int gq = q0 + w * 16 + r;
        float4 v = make_float4(0.f, 0.f, 0.f, 0.f);
        if (gq < SEQ_N) v = *(const float4*)&g_Q[base + (size_t)gq * HDIM + cg];
        int reg = ((r >> 3) & 1) | (((cg >> 2) & 1) << 1);
        uint32_t* pp = &Qw[((cg >> 3) << 7) + ((r & 7) << 4) + reg];
        pp[0]  = f2tf(v.x * 0.125f);
        pp[4]  = f2tf(v.y * 0.125f);
        pp[8]  = f2tf(v.z * 0.125f);
        pp[12] = f2tf(v.w * 0.125f);
    }
    __syncwarp();

    float of[8][4];
#pragma unroll
    for (int i = 0; i < 8; i++)
#pragma unroll
        for (int j = 0; j < 4; j++) of[i][j] = 0.f;
    float m0r = -1e30f, m1r = -1e30f, l0 = 0.f, l1 = 0.f;

    for (int kt = 0; kt < 17; kt++) {
        const int kv0 = kt * 64;
        __syncthreads();
        // ---- stage K, V (64x64 each) packed B-frag layouts ----
#pragma unroll
        for (int it = 0; it < 4; it++) {
            int slot = tid + it * 256;       // 1024 slots = 64 rows x 16 float4
            int r = slot >> 4;               // key index in tile
            int cg = (slot & 15) * 4;        // e
            int gk = kv0 + r;
            float4 kv = make_float4(0.f, 0.f, 0.f, 0.f);
            float4 vv = make_float4(0.f, 0.f, 0.f, 0.f);
            if (gk < SEQ_N) {
                size_t off = base + (size_t)gk * HDIM + cg;
                kv = *(const float4*)&g_K[off];
                vv = *(const float4*)&g_V[off];
            }
            // K: n=key(r), k=e(c)
            {
                uint32_t* pp = &Kpk[(((r >> 3) * 8 + (cg >> 3)) << 6) + ((r & 7) << 3)
                                    + ((cg >> 2) & 1)];
                pp[0] = f2tf(kv.x);
                pp[2] = f2tf(kv.y);
                pp[4] = f2tf(kv.z);
                pp[6] = f2tf(kv.w);
            }
            // V: n=e(c), k=key(r)
            {
                uint32_t* pp = &Vpk[(((cg >> 3) * 8 + (r >> 3)) << 6) + ((cg & 7) << 3)
                                    + ((r & 3) << 1) + ((r >> 2) & 1)];
                pp[0]  = f2tf(vv.x);
                pp[8]  = f2tf(vv.y);
                pp[16] = f2tf(vv.z);
                pp[24] = f2tf(vv.w);
            }
        }
        __syncthreads();

        // ---- S = Q K^T ----
        float s[8][4];
#pragma unroll
        for (int i = 0; i < 8; i++)
#pragma unroll
            for (int j = 0; j < 4; j++) s[i][j] = 0.f;
#pragma unroll
        for (int kb = 0; kb < 8; kb++) {
            uint4 qv = *(const uint4*)&Qw[(kb << 7) + lane * 4];
            uint32_t qa[4] = {qv.x, qv.y, qv.z, qv.w};
#pragma unroll
            for (int nt = 0; nt < 8; nt++) {
                uint2 bv = *(const uint2*)&Kpk[(((nt * 8 + kb)) << 6) + lane * 2];
                uint32_t b[2] = {bv.x, bv.y};
                mma8(s[nt], qa, b);
            }
        }

        if (kt == 16) {
#pragma unroll
            for (int nt = 0; nt < 8; nt++) {
                int col = kv0 + nt * 8 + 2 * (lane & 3);
                if (col >= SEQ_N)     { s[nt][0] = -1e30f; s[nt][2] = -1e30f; }
                if (col + 1 >= SEQ_N) { s[nt][1] = -1e30f; s[nt][3] = -1e30f; }
            }
        }

        // ---- online softmax ----
        float mx0 = -1e30f, mx1 = -1e30f;
#pragma unroll
        for (int nt = 0; nt < 8; nt++) {
            mx0 = fmaxf(mx0, fmaxf(s[nt][0], s[nt][1]));
            mx1 = fmaxf(mx1, fmaxf(s[nt][2], s[nt][3]));
        }
        mx0 = fmaxf(mx0, __shfl_xor_sync(0xffffffffu, mx0, 1));
        mx0 = fmaxf(mx0, __shfl_xor_sync(0xffffffffu, mx0, 2));
        mx1 = fmaxf(mx1, __shfl_xor_sync(0xffffffffu, mx1, 1));
        mx1 = fmaxf(mx1, __shfl_xor_sync(0xffffffffu, mx1, 2));
        float mn0 = fmaxf(m0r, mx0), mn1 = fmaxf(m1r, mx1);
        float cr0 = __expf(m0r - mn0), cr1 = __expf(m1r - mn1);
        float sum0 = 0.f, sum1 = 0.f;
#pragma unroll
        for (int nt = 0; nt < 8; nt++) {
            s[nt][0] = __expf(s[nt][0] - mn0);
            s[nt][1] = __expf(s[nt][1] - mn0);
            s[nt][2] = __expf(s[nt][2] - mn1);
            s[nt][3] = __expf(s[nt][3] - mn1);
            sum0 += s[nt][0] + s[nt][1];
            sum1 += s[nt][2] + s[nt][3];
        }
        sum0 += __shfl_xor_sync(0xffffffffu, sum0, 1);
        sum0 += __shfl_xor_sync(0xffffffffu, sum0, 2);
        sum1 += __shfl_xor_sync(0xffffffffu, sum1, 1);
        sum1 += __shfl_xor_sync(0xffffffffu, sum1, 2);
        l0 = l0 * cr0 + sum0;
        l1 = l1 * cr1 + sum1;
        m0r = mn0;
        m1r = mn1;
#pragma unroll
        for (int ne = 0; ne < 8; ne++) {
            of[ne][0] *= cr0; of[ne][1] *= cr0;
            of[ne][2] *= cr1; of[ne][3] *= cr1;
        }

        // ---- P -> warp-private packed strip ----
        {
            int r0 = lane >> 2;
            int c0 = 2 * (lane & 3);
            int pb = ((r0 << 2) | (c0 & 3)) * 4 + ((c0 & 4) ? 2 : 0);
#pragma unroll
            for (int nt = 0; nt < 8; nt++) {
                uint32_t* pp = &Pw[(nt << 7) + pb];
                pp[0] = f2tf(s[nt][0]);
                pp[4] = f2tf(s[nt][1]);
                pp[1] = f2tf(s[nt][2]);
                pp[5] = f2tf(s[nt][3]);
            }
        }
        __syncwarp();

        // ---- O += P V ----
#pragma unroll
        for (int kb = 0; kb < 8; kb++) {
            uint4 pv = *(const uint4*)&Pw[(kb << 7) + lane * 4];
            uint32_t pa[4] = {pv.x, pv.y, pv.z, pv.w};
#pragma unroll
            for (int ne = 0; ne < 8; ne++) {
                uint2 bv = *(const uint2*)&Vpk[((ne * 8 + kb) << 6) + lane * 2];
                uint32_t b[2] = {bv.x, bv.y};
                mma8(of[ne], pa, b);
            }
        }
        __syncwarp();
    }

    // ---- normalize + write context ----
    float inv0 = 1.f / l0, inv1 = 1.f / l1;
    const int hh = bh % NHEAD;
    const int bb = bh / NHEAD;
    const int qr0 = q0 + w * 16 + (lane >> 2);
    const int qr1 = qr0 + 8;
#pragma unroll
    for (int ne = 0; ne < 8; ne++) {
        int e = hh * 64 + ne * 8 + 2 * (lane & 3);
        if (qr0 < SEQ_N)
            *(float2*)&g_ctx[((size_t)(bb * SEQ_N + qr0)) * DMODEL + e] =
                make_float2(of[ne][0] * inv0, of[ne][1] * inv0);
        if (qr1 < SEQ_N)
            *(float2*)&g_ctx[((size_t)(bb * SEQ_N + qr1)) * DMODEL + e] =
                make_float2(of[ne][2] * inv1, of[ne][3] * inv1);
    }
}

// =================================================================
extern "C" void kernel_launch(void* const* d_in, const int* in_sizes, int n_in,
                              void* d_out, int out_size)
{
    const float* x     = (const float*)d_in[0];
    const float* Wqkv  = (const float*)d_in[1];
    const float* Wproj = (const float*)d_in[2];
    const float* bproj = (const float*)d_in[3];
    const float* freqs = (const float*)d_in[4];
    float* out = (float*)d_out;

    {
        dim3 grid((M_ROWS + 127) / 128, (3 * DMODEL) / 128);
        gemm_tc<0><<<grid, 128>>>(x, Wqkv, nullptr, nullptr, freqs);
    }
    {
        cudaFuncSetAttribute(attn_tc,
                             cudaFuncAttributeMaxDynamicSharedMemorySize,
                             ATTN_SMEM_BYTES);
        dim3 grid((SEQ_N + 127) / 128, NUM_B * NHEAD);
        attn_tc<<<grid, 256, ATTN_SMEM_BYTES>>>();
    }
    {
        dim3 grid((M_ROWS + 127) / 128, DMODEL / 128);
        gemm_tc<1><<<grid, 128>>>(nullptr, Wproj, out, bproj, nullptr);
    }
}